// round 8
// baseline (speedup 1.0000x reference)
#include <cuda_runtime.h>

// MaxUnpooling2D: updates [8,128,128,128] f32, mask [8,128,128,128] i32
// -> out [8,256,256,128] f32.
//
// mask = (y*WOUT + x)*C + f with y=2h+dy, x=2w+dx -> dy=(m>>15)&1, dx=(m>>7)&1.
// Each input element owns its 2x2 output window at its channel: value to (dy,dx),
// zeros elsewhere. Duplicate-free -> no atomics, no init pass, single write per
// output byte. Traffic at the 402 MB information floor.
//
// R7 attribution probe: R4 (v8 loads + v8 stores) regressed with L1 50->75%.
// Loads are latency-critical (sel + all stores depend on them); stores are not.
// Keep proven 128-bit __ldcg loads, widen ONLY stores to st.global.v8.f32:
// thread = 8 channels, 2x LDG.128 each stream, 4x STG.256.

#define B_    8
#define H_    128
#define W_    128
#define C_    128
#define HOUT_ 256
#define WOUT_ 256

// threads = B*H*W*(C/8) = 2,097,152
#define NTHREADS_ (B_ * H_ * W_ * (C_ / 8))

__device__ __forceinline__ void stg_v8(float* __restrict__ p, const float4& a, const float4& b)
{
    asm volatile("st.global.v8.f32 [%0], {%1,%2,%3,%4,%5,%6,%7,%8};"
                 :: "l"(p),
                    "f"(a.x), "f"(a.y), "f"(a.z), "f"(a.w),
                    "f"(b.x), "f"(b.y), "f"(b.z), "f"(b.w)
                 : "memory");
}

__global__ void __launch_bounds__(256) unpool_kernel_s8(
    const float4* __restrict__ upd4,
    const int4*   __restrict__ msk4,
    float*        __restrict__ out)
{
    const unsigned t = blockIdx.x * 256u + threadIdx.x;   // exact grid

    // Two independent 128-bit loads per stream (proven-neutral MLP shape).
    const float4 u0 = __ldcg(upd4 + 2u * t);
    const float4 u1 = __ldcg(upd4 + 2u * t + 1u);
    const int4   m0 = __ldcg(msk4 + 2u * t);
    const int4   m1 = __ldcg(msk4 + 2u * t + 1u);

    // sel = dy*2 + dx per channel
    const int s0 = (((m0.x >> 15) & 1) << 1) | ((m0.x >> 7) & 1);
    const int s1 = (((m0.y >> 15) & 1) << 1) | ((m0.y >> 7) & 1);
    const int s2 = (((m0.z >> 15) & 1) << 1) | ((m0.z >> 7) & 1);
    const int s3 = (((m0.w >> 15) & 1) << 1) | ((m0.w >> 7) & 1);
    const int s4 = (((m1.x >> 15) & 1) << 1) | ((m1.x >> 7) & 1);
    const int s5 = (((m1.y >> 15) & 1) << 1) | ((m1.y >> 7) & 1);
    const int s6 = (((m1.z >> 15) & 1) << 1) | ((m1.z >> 7) & 1);
    const int s7 = (((m1.w >> 15) & 1) << 1) | ((m1.w >> 7) & 1);

    // t -> (b, h, w, c8): c8 = t&15, w = (t>>4)&127, h = (t>>11)&127, b = t>>18
    const unsigned c8 = t & 15u;
    const unsigned w  = (t >> 4) & 127u;
    const unsigned h  = (t >> 11) & 127u;
    const unsigned b  = t >> 18;

    // Output base in floats at window position (0,0)
    const unsigned base = ((b * HOUT_ + 2u * h) * WOUT_ + 2u * w) * C_ + 8u * c8;
    const unsigned rowS = WOUT_ * C_;   // 32768
    const unsigned colS = C_;           // 128

    #pragma unroll
    for (int p = 0; p < 4; ++p) {       // p = py*2 + px
        float4 a, c;
        a.x = (s0 == p) ? u0.x : 0.0f;
        a.y = (s1 == p) ? u0.y : 0.0f;
        a.z = (s2 == p) ? u0.z : 0.0f;
        a.w = (s3 == p) ? u0.w : 0.0f;
        c.x = (s4 == p) ? u1.x : 0.0f;
        c.y = (s5 == p) ? u1.y : 0.0f;
        c.z = (s6 == p) ? u1.z : 0.0f;
        c.w = (s7 == p) ? u1.w : 0.0f;
        const unsigned off = base + (unsigned)(p >> 1) * rowS + (unsigned)(p & 1) * colS;
        stg_v8(out + off, a, c);
    }
}

extern "C" void kernel_launch(void* const* d_in, const int* in_sizes, int n_in,
                              void* d_out, int out_size)
{
    const float4* upd4 = (const float4*)d_in[0];
    const int4*   msk4 = (const int4*)d_in[1];
    float*        out  = (float*)d_out;

    unpool_kernel_s8<<<NTHREADS_ / 256, 256>>>(upd4, msk4, out);
}

// round 9
// speedup vs baseline: 1.0015x; 1.0015x over previous
#include <cuda_runtime.h>

// MaxUnpooling2D: updates [8,128,128,128] f32, mask [8,128,128,128] i32
// -> out [8,256,256,128] f32.
//
// mask = (y*WOUT + x)*C + f with y=2h+dy, x=2w+dx -> dy=(m>>15)&1, dx=(m>>7)&1.
// Each input element owns its 2x2 output window at its channel: value to (dy,dx),
// zeros to the other 3. Duplicate-free -> no atomics, no init pass, every output
// byte written exactly once. Traffic is at the 402 MB information floor.
//
// FINAL (R8 = R5): v4 __ldcg loads + 4x STG.128, block 256, exact grid.
// Probes exhausted: MLP x2 (neutral), v8 load+store (-10%), v8 store-only (-1%),
// .cs hints (neutral), block 512 (neutral). DRAM ~75% of spec = the measured
// mixed 1:2 read:write streaming ceiling; effective rate vs the logical floor
// is ~6.9 TB/s (86% of 8 TB/s) thanks to L2 write absorption.

#define B_    8
#define H_    128
#define W_    128
#define C_    128
#define HOUT_ 256
#define WOUT_ 256

__global__ void __launch_bounds__(256) unpool_kernel(
    const float4* __restrict__ upd4,
    const int4*   __restrict__ msk4,
    float4*       __restrict__ out4)
{
    const unsigned t = blockIdx.x * 256u + threadIdx.x;   // exact grid, no bounds check

    const float4 u = __ldcg(upd4 + t);
    const int4   m = __ldcg(msk4 + t);

    // Per-lane window position code: sel = dy*2 + dx
    const int s0 = (((m.x >> 15) & 1) << 1) | ((m.x >> 7) & 1);
    const int s1 = (((m.y >> 15) & 1) << 1) | ((m.y >> 7) & 1);
    const int s2 = (((m.z >> 15) & 1) << 1) | ((m.z >> 7) & 1);
    const int s3 = (((m.w >> 15) & 1) << 1) | ((m.w >> 7) & 1);

    // t -> (b, h, w, c4): c4 = t&31, w = (t>>5)&127, h = (t>>12)&127, b = t>>19
    const unsigned c4 = t & 31u;
    const unsigned w  = (t >> 5) & 127u;
    const unsigned h  = (t >> 12) & 127u;
    const unsigned b  = t >> 19;

    // Output base (float4 units) of window position (0,0)
    const unsigned base4 = ((b * HOUT_ + 2u * h) * WOUT_ + 2u * w) * (C_ / 4) + c4;
    const unsigned rowS4 = WOUT_ * C_ / 4;   // 8192
    const unsigned colS4 = C_ / 4;           // 32

    #pragma unroll
    for (int p = 0; p < 4; ++p) {            // p = py*2 + px
        float4 v;
        v.x = (s0 == p) ? u.x : 0.0f;
        v.y = (s1 == p) ? u.y : 0.0f;
        v.z = (s2 == p) ? u.z : 0.0f;
        v.w = (s3 == p) ? u.w : 0.0f;
        const unsigned off = base4 + (unsigned)(p >> 1) * rowS4 + (unsigned)(p & 1) * colS4;
        out4[off] = v;
    }
}

extern "C" void kernel_launch(void* const* d_in, const int* in_sizes, int n_in,
                              void* d_out, int out_size)
{
    const float4* upd4 = (const float4*)d_in[0];
    const int4*   msk4 = (const int4*)d_in[1];
    float4*       out4 = (float4*)d_out;

    const unsigned n_threads = (B_ * H_ * W_ * C_) / 4;   // 4,194,304
    unpool_kernel<<<n_threads / 256, 256>>>(upd4, msk4, out4);
}

// round 10
// speedup vs baseline: 1.0045x; 1.0030x over previous
#include <cuda_runtime.h>

// MaxUnpooling2D: updates [8,128,128,128] f32, mask [8,128,128,128] i32
// -> out [8,256,256,128] f32.
//
// mask = (y*WOUT + x)*C + f with y=2h+dy, x=2w+dx -> dy=(m>>15)&1, dx=(m>>7)&1.
// Each input element owns its 2x2 output window at its channel: value to (dy,dx),
// zeros to the other 3. Duplicate-free -> no atomics, no init pass, every output
// byte written exactly once. Traffic is sector-tight at the 402 MB floor (mask
// bits live in every 32B sector -> full mask read unavoidable).
//
// FINAL: v4 __ldcg loads + 4x STG.128, block 256, exact grid.
// Probes exhausted: MLP x2 (neutral), v8 load+store (-10%), v8 store-only (-1%),
// .cs hints (neutral), block 512 (neutral), replication (tie). Kernel 57.5us at
// DRAM ~75% = 6.99 TB/s effective vs logical floor (87% of 8 TB/s spec, boosted
// by L2 write absorption) -> measured mixed-stream ceiling of sm_103a.

#define B_    8
#define H_    128
#define W_    128
#define C_    128
#define HOUT_ 256
#define WOUT_ 256

__global__ void __launch_bounds__(256) unpool_kernel(
    const float4* __restrict__ upd4,
    const int4*   __restrict__ msk4,
    float4*       __restrict__ out4)
{
    const unsigned t = blockIdx.x * 256u + threadIdx.x;   // exact grid, no bounds check

    const float4 u = __ldcg(upd4 + t);
    const int4   m = __ldcg(msk4 + t);

    // Per-lane window position code: sel = dy*2 + dx
    const int s0 = (((m.x >> 15) & 1) << 1) | ((m.x >> 7) & 1);
    const int s1 = (((m.y >> 15) & 1) << 1) | ((m.y >> 7) & 1);
    const int s2 = (((m.z >> 15) & 1) << 1) | ((m.z >> 7) & 1);
    const int s3 = (((m.w >> 15) & 1) << 1) | ((m.w >> 7) & 1);

    // t -> (b, h, w, c4): c4 = t&31, w = (t>>5)&127, h = (t>>12)&127, b = t>>19
    const unsigned c4 = t & 31u;
    const unsigned w  = (t >> 5) & 127u;
    const unsigned h  = (t >> 12) & 127u;
    const unsigned b  = t >> 19;

    // Output base (float4 units) of window position (0,0)
    const unsigned base4 = ((b * HOUT_ + 2u * h) * WOUT_ + 2u * w) * (C_ / 4) + c4;
    const unsigned rowS4 = WOUT_ * C_ / 4;   // 8192
    const unsigned colS4 = C_ / 4;           // 32

    #pragma unroll
    for (int p = 0; p < 4; ++p) {            // p = py*2 + px
        float4 v;
        v.x = (s0 == p) ? u.x : 0.0f;
        v.y = (s1 == p) ? u.y : 0.0f;
        v.z = (s2 == p) ? u.z : 0.0f;
        v.w = (s3 == p) ? u.w : 0.0f;
        const unsigned off = base4 + (unsigned)(p >> 1) * rowS4 + (unsigned)(p & 1) * colS4;
        out4[off] = v;
    }
}

extern "C" void kernel_launch(void* const* d_in, const int* in_sizes, int n_in,
                              void* d_out, int out_size)
{
    const float4* upd4 = (const float4*)d_in[0];
    const int4*   msk4 = (const int4*)d_in[1];
    float4*       out4 = (float4*)d_out;

    const unsigned n_threads = (B_ * H_ * W_ * C_) / 4;   // 4,194,304
    unpool_kernel<<<n_threads / 256, 256>>>(upd4, msk4, out4);
}